// round 4
// baseline (speedup 1.0000x reference)
#include <cuda_runtime.h>
#include <cstdint>

// Problem constants
#define BS  8
#define SEQ 512
#define C   512
#define NC  5
#define H   768
#define W   768
#define HW  (H * W)            // 589824
#define NTOK (BS * SEQ)        // 4096

// Scratch (device globals — no allocation allowed)
__device__ unsigned char g_labels[BS * HW];   // per-pixel argmax label
__device__ int           g_maj[NTOK];          // per-token majority label
__device__ float         g_nll[NTOK];          // per-token masked nll

// ---------------------------------------------------------------------------
// Kernel 1: per-pixel argmax over NC channels -> uint8 label map
// class_labels layout: [BS, NC, H, W]. 4 pixels per thread via float4.
// ---------------------------------------------------------------------------
__global__ void label_argmax_kernel(const float* __restrict__ cls) {
    int idx = blockIdx.x * blockDim.x + threadIdx.x;   // one per 4 pixels
    const int total4 = BS * HW / 4;
    if (idx >= total4) return;
    int p = idx * 4;
    int b = p / HW;
    int r = p - b * HW;
    const float* base = cls + (size_t)b * NC * HW + r;

    float4 best = *(const float4*)(base);
    uchar4 lab = make_uchar4(0, 0, 0, 0);
#pragma unroll
    for (int c = 1; c < NC; c++) {
        float4 v = *(const float4*)(base + (size_t)c * HW);
        if (v.x > best.x) { best.x = v.x; lab.x = (unsigned char)c; }
        if (v.y > best.y) { best.y = v.y; lab.y = (unsigned char)c; }
        if (v.z > best.z) { best.z = v.z; lab.z = (unsigned char)c; }
        if (v.w > best.w) { best.w = v.w; lab.w = (unsigned char)c; }
    }
    *(uchar4*)(g_labels + (size_t)b * HW + r) = lab;
}

// ---------------------------------------------------------------------------
// Kernel 2: one warp per box -> majority label (first-max tiebreak)
// ---------------------------------------------------------------------------
__global__ void box_vote_kernel(const int* __restrict__ coords) {
    int warp_id = (blockIdx.x * blockDim.x + threadIdx.x) >> 5;
    int lane = threadIdx.x & 31;
    if (warp_id >= NTOK) return;
    int t = warp_id;
    int b = t / SEQ;

    int x0 = coords[t * 4 + 0];
    int y0 = coords[t * 4 + 1];
    int x1 = coords[t * 4 + 2];
    int y1 = coords[t * 4 + 3];
    if (y1 == y0) y1 = y0 + 1;   // degenerate-box fix (reference semantics)
    if (x1 == x0) x1 = x0 + 1;

    int wbox = x1 - x0;
    int hbox = y1 - y0;
    int area = wbox * hbox;
    const unsigned char* lb = g_labels + (size_t)b * HW;

    int cnt[NC];
#pragma unroll
    for (int c = 0; c < NC; c++) cnt[c] = 0;

    for (int i = lane; i < area; i += 32) {
        int yy = y0 + i / wbox;
        int xx = x0 + i - (i / wbox) * wbox;
        unsigned char l = lb[yy * W + xx];
#pragma unroll
        for (int c = 0; c < NC; c++) cnt[c] += (l == c);
    }
#pragma unroll
    for (int c = 0; c < NC; c++) cnt[c] = __reduce_add_sync(0xffffffffu, cnt[c]);

    if (lane == 0) {
        int best = cnt[0], bi = 0;
#pragma unroll
        for (int c = 1; c < NC; c++)
            if (cnt[c] > best) { best = cnt[c]; bi = c; }   // strict > : first-max
        g_maj[t] = bi;
    }
}

// ---------------------------------------------------------------------------
// Kernel 3: one warp per token: logits = emb . Wc^T + bc, then masked nll.
// Wc [NC, C] cached in shared. 8 warps (8 tokens) per 256-thread block.
// ---------------------------------------------------------------------------
__global__ void __launch_bounds__(256) logits_ce_kernel(
    const float* __restrict__ emb, const float* __restrict__ Wc,
    const float* __restrict__ bc, const int* __restrict__ mask) {
    __shared__ float sW[NC * C];   // 10 KB
    for (int i = threadIdx.x; i < NC * C; i += blockDim.x) sW[i] = Wc[i];
    __syncthreads();

    int warp_in_blk = threadIdx.x >> 5;
    int lane = threadIdx.x & 31;
    int t = blockIdx.x * 8 + warp_in_blk;
    if (t >= NTOK) return;

    const float4* e4 = (const float4*)(emb + (size_t)t * C);   // 128 float4s
    float acc[NC];
#pragma unroll
    for (int c = 0; c < NC; c++) acc[c] = 0.f;

#pragma unroll
    for (int k = 0; k < 4; k++) {
        int i = lane + 32 * k;
        float4 v = e4[i];
#pragma unroll
        for (int c = 0; c < NC; c++) {
            float4 w = ((const float4*)(sW + c * C))[i];
            acc[c] += v.x * w.x + v.y * w.y + v.z * w.z + v.w * w.w;
        }
    }
#pragma unroll
    for (int c = 0; c < NC; c++) {
#pragma unroll
        for (int o = 16; o > 0; o >>= 1)
            acc[c] += __shfl_down_sync(0xffffffffu, acc[c], o);
    }

    if (lane == 0) {
        float l[NC];
        float m = -1e30f;
#pragma unroll
        for (int c = 0; c < NC; c++) { l[c] = acc[c] + bc[c]; m = fmaxf(m, l[c]); }
        float s = 0.f;
#pragma unroll
        for (int c = 0; c < NC; c++) s += __expf(l[c] - m);
        int mj = g_maj[t];
        float nll = -(l[mj] - m) + __logf(s);
        g_nll[t] = (mask[t] == 1) ? nll : 0.f;
    }
}

// ---------------------------------------------------------------------------
// Kernel 4: single-block deterministic reduction -> scalar out
// ---------------------------------------------------------------------------
__global__ void __launch_bounds__(256) reduce_kernel(
    const int* __restrict__ mask, float* __restrict__ out) {
    __shared__ float ssum[256];
    __shared__ int smsk[256];
    float s = 0.f;
    int mk = 0;
    for (int i = threadIdx.x; i < NTOK; i += 256) {
        s += g_nll[i];
        mk += (mask[i] == 1);
    }
    ssum[threadIdx.x] = s;
    smsk[threadIdx.x] = mk;
    __syncthreads();
    for (int o = 128; o > 0; o >>= 1) {
        if (threadIdx.x < o) {
            ssum[threadIdx.x] += ssum[threadIdx.x + o];
            smsk[threadIdx.x] += smsk[threadIdx.x + o];
        }
        __syncthreads();
    }
    if (threadIdx.x == 0) out[0] = ssum[0] / (float)smsk[0];
}

// ---------------------------------------------------------------------------
extern "C" void kernel_launch(void* const* d_in, const int* in_sizes, int n_in,
                              void* d_out, int out_size) {
    const float* emb    = (const float*)d_in[0];   // [8,512,512]
    const float* cls    = (const float*)d_in[1];   // [8,5,768,768]
    const float* Wc     = (const float*)d_in[2];   // [5,512]
    const float* bc     = (const float*)d_in[3];   // [5]
    const int*   coords = (const int*)d_in[4];     // [8,512,4]
    const int*   mask   = (const int*)d_in[5];     // [8,512]
    float* out = (float*)d_out;

    {
        int total4 = BS * HW / 4;
        int threads = 256;
        int blocks = (total4 + threads - 1) / threads;
        label_argmax_kernel<<<blocks, threads>>>(cls);
    }
    {
        // one warp per box: 4096 warps -> 512 blocks x 256 threads
        box_vote_kernel<<<(NTOK * 32 + 255) / 256, 256>>>(coords);
    }
    {
        logits_ce_kernel<<<NTOK / 8, 256>>>(emb, Wc, bc, mask);
    }
    {
        reduce_kernel<<<1, 256>>>(mask, out);
    }
}

// round 6
// speedup vs baseline: 1.0481x; 1.0481x over previous
#include <cuda_runtime.h>
#include <cstdint>

// Problem constants
#define BS  8
#define SEQ 512
#define C   512
#define NC  5
#define H   768
#define W   768
#define HW  (H * W)            // 589824
#define NTOK (BS * SEQ)        // 4096
#define NBLK (NTOK / 8)        // 512 blocks in fused kernel (8 tokens/block)

// Scratch (device globals — no allocation allowed)
__device__ unsigned char g_labels[BS * HW];   // per-pixel argmax label
__device__ float         g_part[NBLK];        // per-block masked-nll partial
__device__ int           g_pcnt[NBLK];        // per-block mask count
__device__ int           g_counter = 0;       // arrival counter (self-resetting)

// ---------------------------------------------------------------------------
// Kernel 1: per-pixel argmax over NC channels -> uint8 label map
// class_labels layout: [BS, NC, H, W]. 4 pixels per thread via float4.
// ---------------------------------------------------------------------------
__global__ void label_argmax_kernel(const float* __restrict__ cls) {
    int idx = blockIdx.x * blockDim.x + threadIdx.x;   // one per 4 pixels
    const int total4 = BS * HW / 4;
    if (idx >= total4) return;
    int p = idx * 4;
    int b = p / HW;
    int r = p - b * HW;
    const float* base = cls + (size_t)b * NC * HW + r;

    float4 best = *(const float4*)(base);
    uchar4 lab = make_uchar4(0, 0, 0, 0);
#pragma unroll
    for (int c = 1; c < NC; c++) {
        float4 v = *(const float4*)(base + (size_t)c * HW);
        if (v.x > best.x) { best.x = v.x; lab.x = (unsigned char)c; }
        if (v.y > best.y) { best.y = v.y; lab.y = (unsigned char)c; }
        if (v.z > best.z) { best.z = v.z; lab.z = (unsigned char)c; }
        if (v.w > best.w) { best.w = v.w; lab.w = (unsigned char)c; }
    }
    *(uchar4*)(g_labels + (size_t)b * HW + r) = lab;
}

// ---------------------------------------------------------------------------
// Kernel 2 (fused): per-warp box vote + logits + CE, per-block partial,
// last block does the final reduction and writes the scalar output.
// 8 warps = 8 tokens per 256-thread block.
// ---------------------------------------------------------------------------
__global__ void __launch_bounds__(256) fused_vote_ce_kernel(
    const float* __restrict__ emb, const float* __restrict__ Wc,
    const float* __restrict__ bc, const int* __restrict__ coords,
    const int* __restrict__ mask, float* __restrict__ out) {
    __shared__ float sW[NC * C];   // 10 KB
    __shared__ float wnll[8];
    __shared__ int   wmsk[8];
    __shared__ int   sdone;

    // Issue Wc shared-load; visibility deferred until after the vote phase.
    for (int i = threadIdx.x; i < NC * C; i += blockDim.x) sW[i] = Wc[i];

    int wib  = threadIdx.x >> 5;
    int lane = threadIdx.x & 31;
    int t = blockIdx.x * 8 + wib;
    int b = t / SEQ;

    // ---- box majority vote (no divides: row loop, lanes stride x) ----
    int4 cd = ((const int4*)coords)[t];
    int x0 = cd.x, y0 = cd.y, x1 = cd.z, y1 = cd.w;
    if (y1 == y0) y1++;          // degenerate-box fix (reference semantics)
    if (x1 == x0) x1++;

    const unsigned char* lb = g_labels + (size_t)b * HW;
    int cnt[NC];
#pragma unroll
    for (int c = 0; c < NC; c++) cnt[c] = 0;

    for (int yy = y0; yy < y1; yy++) {
        const unsigned char* row = lb + yy * W;
        for (int xx = x0 + lane; xx < x1; xx += 32) {
            int l = row[xx];
#pragma unroll
            for (int c = 0; c < NC; c++) cnt[c] += (l == c);
        }
    }
#pragma unroll
    for (int c = 0; c < NC; c++) cnt[c] = __reduce_add_sync(0xffffffffu, cnt[c]);

    int maj = 0, bestc = cnt[0];
#pragma unroll
    for (int c = 1; c < NC; c++)
        if (cnt[c] > bestc) { bestc = cnt[c]; maj = c; }   // strict > : first-max

    __syncthreads();   // sW now visible

    // ---- logits: warp-parallel dot over C=512 ----
    const float4* e4 = (const float4*)(emb + (size_t)t * C);   // 128 float4s
    float acc[NC];
#pragma unroll
    for (int c = 0; c < NC; c++) acc[c] = 0.f;

#pragma unroll
    for (int k = 0; k < 4; k++) {
        int i = lane + 32 * k;
        float4 v = e4[i];
#pragma unroll
        for (int c = 0; c < NC; c++) {
            float4 w = ((const float4*)(sW + c * C))[i];
            acc[c] += v.x * w.x + v.y * w.y + v.z * w.z + v.w * w.w;
        }
    }
#pragma unroll
    for (int c = 0; c < NC; c++) {
#pragma unroll
        for (int o = 16; o > 0; o >>= 1)
            acc[c] += __shfl_down_sync(0xffffffffu, acc[c], o);
    }

    if (lane == 0) {
        float l[NC];
        float m = -1e30f;
#pragma unroll
        for (int c = 0; c < NC; c++) { l[c] = acc[c] + bc[c]; m = fmaxf(m, l[c]); }
        float s = 0.f;
#pragma unroll
        for (int c = 0; c < NC; c++) s += __expf(l[c] - m);
        float nll = -(l[maj] - m) + __logf(s);
        int mk = (mask[t] == 1);
        wnll[wib] = mk ? nll : 0.f;
        wmsk[wib] = mk;
    }
    __syncthreads();

    // ---- per-block partial + last-block final reduce ----
    if (threadIdx.x == 0) {
        float s = 0.f;
        int c = 0;
#pragma unroll
        for (int i = 0; i < 8; i++) { s += wnll[i]; c += wmsk[i]; }
        g_part[blockIdx.x] = s;
        g_pcnt[blockIdx.x] = c;
        __threadfence();
        int old = atomicAdd(&g_counter, 1);
        sdone = (old == NBLK - 1);
    }
    __syncthreads();

    if (sdone) {
        __shared__ float fs[256];
        __shared__ int   fc[256];
        int tid = threadIdx.x;
        fs[tid] = g_part[tid] + g_part[tid + 256];
        fc[tid] = g_pcnt[tid] + g_pcnt[tid + 256];
        __syncthreads();
        for (int o = 128; o > 0; o >>= 1) {
            if (tid < o) { fs[tid] += fs[tid + o]; fc[tid] += fc[tid + o]; }
            __syncthreads();
        }
        if (tid == 0) {
            out[0] = fs[0] / (float)fc[0];
            g_counter = 0;   // reset for next graph replay (deterministic)
        }
    }
}

// ---------------------------------------------------------------------------
extern "C" void kernel_launch(void* const* d_in, const int* in_sizes, int n_in,
                              void* d_out, int out_size) {
    const float* emb    = (const float*)d_in[0];   // [8,512,512]
    const float* cls    = (const float*)d_in[1];   // [8,5,768,768]
    const float* Wc     = (const float*)d_in[2];   // [5,512]
    const float* bc     = (const float*)d_in[3];   // [5]
    const int*   coords = (const int*)d_in[4];     // [8,512,4]
    const int*   mask   = (const int*)d_in[5];     // [8,512]
    float* out = (float*)d_out;

    {
        int total4 = BS * HW / 4;
        int threads = 256;
        int blocks = (total4 + threads - 1) / threads;
        label_argmax_kernel<<<blocks, threads>>>(cls);
    }
    fused_vote_ce_kernel<<<NBLK, 256>>>(emb, Wc, bc, coords, mask, out);
}